// round 1
// baseline (speedup 1.0000x reference)
#include <cuda_runtime.h>
#include <math.h>

// Problem constants
// feature  [64, 60, 512]  f32
// captions [64, 20]       i32
// embedding[32000, 512]   f32
// W_ih     [2048, 1024]   f32
// W_hh     [2048, 512]    f32
// b_ih     [2048], b_hh [2048]
// W_lin    [32000, 512], b_lin [32000]
// out      [1216, 32000]  f32   (rows = b*19 + t', t' = 0..18 -> global t = 40..58)

#define BATCH 64
#define TSTEPS 60
#define MAXFRAME 40
#define CAPLEN 20
#define HDIM 512
#define EDIM 512
#define XDIM 1024
#define GDIM 2048
#define VOCAB 32000
#define OUTROWS 1216  // 64 * 19

// -------- device scratch (no allocations allowed) --------
__device__ float g_X[TSTEPS * BATCH * XDIM];      // 15.7 MB  xs materialized [t*64+b][1024]
__device__ float g_G[TSTEPS * BATCH * GDIM];      // 31.5 MB  precomputed x-gates + bias
__device__ float g_bias[GDIM];                    // b_ih + b_hh
__device__ float g_h[BATCH * HDIM];
__device__ float g_c[BATCH * HDIM];
__device__ float g_part[4 * BATCH * GDIM];        // k-split partials of h @ W_hh^T
__device__ float g_dech[OUTROWS * HDIM];          // decoder hiddens, row = b*19 + (t-40)

// ---------------------------------------------------------------------------
// Build xs: X[t*64+b][0:512]  = (t<40) ? 0 : embedding[captions[b][t-40]]
//           X[t*64+b][512:1024] = feature[b][t]
// ---------------------------------------------------------------------------
__global__ void build_x_kernel(const float* __restrict__ feature,
                               const int* __restrict__ captions,
                               const float* __restrict__ embedding) {
    int idx = blockIdx.x * blockDim.x + threadIdx.x;   // float4 index
    // total float4 = 60*64*1024/4 = 983040
    int r  = idx >> 8;      // row (t*64+b), 256 float4 per row
    int c4 = idx & 255;     // float4 col within row
    int t = r >> 6;
    int b = r & 63;
    float4 v = make_float4(0.f, 0.f, 0.f, 0.f);
    if (c4 < 128) {
        if (t >= MAXFRAME) {
            int cap = captions[b * CAPLEN + (t - MAXFRAME)];
            v = *(const float4*)&embedding[(size_t)cap * EDIM + c4 * 4];
        }
    } else {
        v = *(const float4*)&feature[((size_t)b * TSTEPS + t) * HDIM + (c4 - 128) * 4];
    }
    *(float4*)&g_X[(size_t)r * XDIM + c4 * 4] = v;
}

// ---------------------------------------------------------------------------
// Prep: zero h, c; combined bias
// ---------------------------------------------------------------------------
__global__ void prep_kernel(const float* __restrict__ b_ih,
                            const float* __restrict__ b_hh) {
    int idx = blockIdx.x * blockDim.x + threadIdx.x;
    if (idx < BATCH * HDIM) {
        g_h[idx] = 0.f;
        g_c[idx] = 0.f;
    }
    if (idx < GDIM) {
        g_bias[idx] = b_ih[idx] + b_hh[idx];
    }
}

// ---------------------------------------------------------------------------
// Generic tiled SGEMM:  C[M,N] = A[M,K] * B[N,K]^T + bias[N]
// A row-major [M,K], B row-major [N,K] (i.e. both K-contiguous).
// Tiles: 128x128x16, 256 threads, 8x8 microtile.
// Requires: N % 128 == 0, K % 16 == 0.  M boundary handled.
// ---------------------------------------------------------------------------
__global__ void __launch_bounds__(256, 2)
sgemm_nt(const float* __restrict__ A, const float* __restrict__ B,
         const float* __restrict__ bias, float* __restrict__ C,
         int M, int N, int K) {
    __shared__ float As[16][132];
    __shared__ float Bs[16][132];

    const int tid = threadIdx.x;
    const int bm = blockIdx.y * 128;
    const int bn = blockIdx.x * 128;
    const int tx = tid & 15;
    const int ty = tid >> 4;
    const int lr = tid >> 2;   // 0..63
    const int lc = tid & 3;    // float4 column (0..3) within 16-wide K chunk

    float acc[8][8];
#pragma unroll
    for (int i = 0; i < 8; i++)
#pragma unroll
        for (int j = 0; j < 8; j++) acc[i][j] = 0.f;

    for (int k0 = 0; k0 < K; k0 += 16) {
#pragma unroll
        for (int i = 0; i < 2; i++) {
            int row = lr + 64 * i;
            int gm = bm + row;
            float4 va = make_float4(0.f, 0.f, 0.f, 0.f);
            if (gm < M) va = *(const float4*)&A[(size_t)gm * K + k0 + lc * 4];
            As[lc * 4 + 0][row] = va.x;
            As[lc * 4 + 1][row] = va.y;
            As[lc * 4 + 2][row] = va.z;
            As[lc * 4 + 3][row] = va.w;
            float4 vb = *(const float4*)&B[(size_t)(bn + row) * K + k0 + lc * 4];
            Bs[lc * 4 + 0][row] = vb.x;
            Bs[lc * 4 + 1][row] = vb.y;
            Bs[lc * 4 + 2][row] = vb.z;
            Bs[lc * 4 + 3][row] = vb.w;
        }
        __syncthreads();
#pragma unroll
        for (int k = 0; k < 16; k++) {
            float4 a0 = *(const float4*)&As[k][ty * 8];
            float4 a1 = *(const float4*)&As[k][ty * 8 + 4];
            float4 b0 = *(const float4*)&Bs[k][tx * 8];
            float4 b1 = *(const float4*)&Bs[k][tx * 8 + 4];
            float av[8] = {a0.x, a0.y, a0.z, a0.w, a1.x, a1.y, a1.z, a1.w};
            float bv[8] = {b0.x, b0.y, b0.z, b0.w, b1.x, b1.y, b1.z, b1.w};
#pragma unroll
            for (int i = 0; i < 8; i++)
#pragma unroll
                for (int j = 0; j < 8; j++) acc[i][j] += av[i] * bv[j];
        }
        __syncthreads();
    }

#pragma unroll
    for (int i = 0; i < 8; i++) {
        int gm = bm + ty * 8 + i;
        if (gm >= M) break;
#pragma unroll
        for (int jq = 0; jq < 2; jq++) {
            int gc = bn + tx * 8 + jq * 4;
            float4 o;
            o.x = acc[i][jq * 4 + 0] + bias[gc + 0];
            o.y = acc[i][jq * 4 + 1] + bias[gc + 1];
            o.z = acc[i][jq * 4 + 2] + bias[gc + 2];
            o.w = acc[i][jq * 4 + 3] + bias[gc + 3];
            *(float4*)&C[(size_t)gm * N + gc] = o;
        }
    }
}

// ---------------------------------------------------------------------------
// Recurrence GEMM: partials of  h[64,512] @ W_hh[2048,512]^T
// grid = (32 n-tiles of 64, 4 k-splits of 128). 256 threads, 4x4 microtile.
// Writes g_part[ksplit][batch][gatecol].
// ---------------------------------------------------------------------------
__global__ void __launch_bounds__(256, 4)
lstm_hgemm(const float* __restrict__ W_hh) {
    __shared__ float Hs[32][72];
    __shared__ float Ws[32][72];
    const int tid = threadIdx.x;
    const int n0 = blockIdx.x * 64;
    const int k0 = blockIdx.y * 128;
    const int tx = tid & 15;
    const int ty = tid >> 4;

    float acc[4][4];
#pragma unroll
    for (int i = 0; i < 4; i++)
#pragma unroll
        for (int j = 0; j < 4; j++) acc[i][j] = 0.f;

    for (int kk = 0; kk < 128; kk += 32) {
#pragma unroll
        for (int i = 0; i < 2; i++) {
            int idx = tid + 256 * i;
            int row = idx >> 3;    // 0..63
            int c4  = idx & 7;     // 0..7
            float4 v = *(const float4*)&g_h[row * HDIM + k0 + kk + c4 * 4];
            Hs[c4 * 4 + 0][row] = v.x;
            Hs[c4 * 4 + 1][row] = v.y;
            Hs[c4 * 4 + 2][row] = v.z;
            Hs[c4 * 4 + 3][row] = v.w;
            float4 w = *(const float4*)&W_hh[(size_t)(n0 + row) * HDIM + k0 + kk + c4 * 4];
            Ws[c4 * 4 + 0][row] = w.x;
            Ws[c4 * 4 + 1][row] = w.y;
            Ws[c4 * 4 + 2][row] = w.z;
            Ws[c4 * 4 + 3][row] = w.w;
        }
        __syncthreads();
#pragma unroll
        for (int k = 0; k < 32; k++) {
            float4 a = *(const float4*)&Hs[k][ty * 4];
            float4 b = *(const float4*)&Ws[k][tx * 4];
            float av[4] = {a.x, a.y, a.z, a.w};
            float bv[4] = {b.x, b.y, b.z, b.w};
#pragma unroll
            for (int i = 0; i < 4; i++)
#pragma unroll
                for (int j = 0; j < 4; j++) acc[i][j] += av[i] * bv[j];
        }
        __syncthreads();
    }

    float* outp = &g_part[((size_t)blockIdx.y * BATCH + ty * 4) * GDIM + n0 + tx * 4];
#pragma unroll
    for (int i = 0; i < 4; i++) {
        float4 o = make_float4(acc[i][0], acc[i][1], acc[i][2], acc[i][3]);
        *(float4*)&outp[(size_t)i * GDIM] = o;
    }
}

// ---------------------------------------------------------------------------
// LSTM cell: gates = G[t] + sum_k g_part[k]; update h, c; stash decoder h.
// ---------------------------------------------------------------------------
__device__ __forceinline__ float sigmoidf_(float x) {
    return 1.f / (1.f + expf(-x));
}

__global__ void lstm_cell(int t) {
    int idx = blockIdx.x * blockDim.x + threadIdx.x;  // 0 .. 64*512-1
    int b = idx >> 9;
    int j = idx & 511;
    const float* G = &g_G[((size_t)t * BATCH + b) * GDIM];
    float gi = G[j];
    float gf = G[512 + j];
    float gg = G[1024 + j];
    float go = G[1536 + j];
#pragma unroll
    for (int ks = 0; ks < 4; ks++) {
        const float* P = &g_part[((size_t)ks * BATCH + b) * GDIM];
        gi += P[j];
        gf += P[512 + j];
        gg += P[1024 + j];
        go += P[1536 + j];
    }
    float c = g_c[idx];
    float cn = sigmoidf_(gf) * c + sigmoidf_(gi) * tanhf(gg);
    float hn = sigmoidf_(go) * tanhf(cn);
    g_c[idx] = cn;
    g_h[idx] = hn;
    if (t >= MAXFRAME && t < MAXFRAME + CAPLEN - 1) {
        g_dech[((size_t)b * (CAPLEN - 1) + (t - MAXFRAME)) * HDIM + j] = hn;
    }
}

// ---------------------------------------------------------------------------
// launch
// ---------------------------------------------------------------------------
extern "C" void kernel_launch(void* const* d_in, const int* in_sizes, int n_in,
                              void* d_out, int out_size) {
    const float* feature   = (const float*)d_in[0];
    const int*   captions  = (const int*)d_in[1];
    const float* embedding = (const float*)d_in[2];
    const float* W_ih      = (const float*)d_in[3];
    const float* W_hh      = (const float*)d_in[4];
    const float* b_ih      = (const float*)d_in[5];
    const float* b_hh      = (const float*)d_in[6];
    const float* W_lin     = (const float*)d_in[7];
    const float* b_lin     = (const float*)d_in[8];
    float* out = (float*)d_out;

    void *pX, *pG, *pBias, *pDecH;
    cudaGetSymbolAddress(&pX, g_X);
    cudaGetSymbolAddress(&pG, g_G);
    cudaGetSymbolAddress(&pBias, g_bias);
    cudaGetSymbolAddress(&pDecH, g_dech);

    // 1) materialize xs
    build_x_kernel<<<3840, 256>>>(feature, captions, embedding);
    // 2) zero state + combined bias
    prep_kernel<<<128, 256>>>(b_ih, b_hh);
    // 3) all input-side gates in one GEMM: [3840,1024] x [1024,2048]^T
    sgemm_nt<<<dim3(GDIM / 128, (TSTEPS * BATCH) / 128), 256>>>(
        (const float*)pX, W_ih, (const float*)pBias, (float*)pG,
        TSTEPS * BATCH, GDIM, XDIM);
    // 4) sequential recurrence: 60 x (h-GEMM + cell)
    for (int t = 0; t < TSTEPS; t++) {
        lstm_hgemm<<<dim3(32, 4), 256>>>(W_hh);
        lstm_cell<<<64, 512>>>(t);
    }
    // 5) projection: [1216,512] x [512,32000]^T + b_lin
    sgemm_nt<<<dim3(VOCAB / 128, (OUTROWS + 127) / 128), 256>>>(
        (const float*)pDecH, W_lin, b_lin, out,
        OUTROWS, VOCAB, HDIM);
}

// round 2
// speedup vs baseline: 1.0002x; 1.0002x over previous
#include <cuda_runtime.h>
#include <math.h>

// Problem constants
// feature  [64, 60, 512]  f32
// captions [64, 20]       i32
// embedding[32000, 512]   f32
// W_ih     [2048, 1024]   f32
// W_hh     [2048, 512]    f32
// b_ih     [2048], b_hh [2048]
// W_lin    [32000, 512], b_lin [32000]
// out      [1216, 32000]  f32   (rows = b*19 + t', t' = 0..18 -> global t = 40..58)

#define BATCH 64
#define TSTEPS 60
#define MAXFRAME 40
#define CAPLEN 20
#define HDIM 512
#define EDIM 512
#define XDIM 1024
#define GDIM 2048
#define VOCAB 32000
#define OUTROWS 1216  // 64 * 19

// -------- device scratch (no allocations allowed) --------
__device__ float g_X[TSTEPS * BATCH * XDIM];      // 15.7 MB  xs materialized [t*64+b][1024]
__device__ float g_G[TSTEPS * BATCH * GDIM];      // 31.5 MB  precomputed x-gates + bias
__device__ float g_bias[GDIM];                    // b_ih + b_hh
__device__ float g_h[BATCH * HDIM];
__device__ float g_c[BATCH * HDIM];
__device__ float g_part[4 * BATCH * GDIM];        // k-split partials of h @ W_hh^T
__device__ float g_dech[OUTROWS * HDIM];          // decoder hiddens, row = b*19 + (t-40)

// ---------------------------------------------------------------------------
// Build xs: X[t*64+b][0:512]  = (t<40) ? 0 : embedding[captions[b][t-40]]
//           X[t*64+b][512:1024] = feature[b][t]
// ---------------------------------------------------------------------------
__global__ void build_x_kernel(const float* __restrict__ feature,
                               const int* __restrict__ captions,
                               const float* __restrict__ embedding) {
    int idx = blockIdx.x * blockDim.x + threadIdx.x;   // float4 index
    // total float4 = 60*64*1024/4 = 983040
    int r  = idx >> 8;      // row (t*64+b), 256 float4 per row
    int c4 = idx & 255;     // float4 col within row
    int t = r >> 6;
    int b = r & 63;
    float4 v = make_float4(0.f, 0.f, 0.f, 0.f);
    if (c4 < 128) {
        if (t >= MAXFRAME) {
            int cap = captions[b * CAPLEN + (t - MAXFRAME)];
            v = *(const float4*)&embedding[(size_t)cap * EDIM + c4 * 4];
        }
    } else {
        v = *(const float4*)&feature[((size_t)b * TSTEPS + t) * HDIM + (c4 - 128) * 4];
    }
    *(float4*)&g_X[(size_t)r * XDIM + c4 * 4] = v;
}

// ---------------------------------------------------------------------------
// Prep: zero h, c; combined bias
// ---------------------------------------------------------------------------
__global__ void prep_kernel(const float* __restrict__ b_ih,
                            const float* __restrict__ b_hh) {
    int idx = blockIdx.x * blockDim.x + threadIdx.x;
    if (idx < BATCH * HDIM) {
        g_h[idx] = 0.f;
        g_c[idx] = 0.f;
    }
    if (idx < GDIM) {
        g_bias[idx] = b_ih[idx] + b_hh[idx];
    }
}

// ---------------------------------------------------------------------------
// Generic tiled SGEMM:  C[M,N] = A[M,K] * B[N,K]^T + bias[N]
// A row-major [M,K], B row-major [N,K] (i.e. both K-contiguous).
// Tiles: 128x128x16, 256 threads, 8x8 microtile.
// Requires: N % 128 == 0, K % 16 == 0.  M boundary handled.
// ---------------------------------------------------------------------------
__global__ void __launch_bounds__(256, 2)
sgemm_nt(const float* __restrict__ A, const float* __restrict__ B,
         const float* __restrict__ bias, float* __restrict__ C,
         int M, int N, int K) {
    __shared__ float As[16][132];
    __shared__ float Bs[16][132];

    const int tid = threadIdx.x;
    const int bm = blockIdx.y * 128;
    const int bn = blockIdx.x * 128;
    const int tx = tid & 15;
    const int ty = tid >> 4;
    const int lr = tid >> 2;   // 0..63
    const int lc = tid & 3;    // float4 column (0..3) within 16-wide K chunk

    float acc[8][8];
#pragma unroll
    for (int i = 0; i < 8; i++)
#pragma unroll
        for (int j = 0; j < 8; j++) acc[i][j] = 0.f;

    for (int k0 = 0; k0 < K; k0 += 16) {
#pragma unroll
        for (int i = 0; i < 2; i++) {
            int row = lr + 64 * i;
            int gm = bm + row;
            float4 va = make_float4(0.f, 0.f, 0.f, 0.f);
            if (gm < M) va = *(const float4*)&A[(size_t)gm * K + k0 + lc * 4];
            As[lc * 4 + 0][row] = va.x;
            As[lc * 4 + 1][row] = va.y;
            As[lc * 4 + 2][row] = va.z;
            As[lc * 4 + 3][row] = va.w;
            float4 vb = *(const float4*)&B[(size_t)(bn + row) * K + k0 + lc * 4];
            Bs[lc * 4 + 0][row] = vb.x;
            Bs[lc * 4 + 1][row] = vb.y;
            Bs[lc * 4 + 2][row] = vb.z;
            Bs[lc * 4 + 3][row] = vb.w;
        }
        __syncthreads();
#pragma unroll
        for (int k = 0; k < 16; k++) {
            float4 a0 = *(const float4*)&As[k][ty * 8];
            float4 a1 = *(const float4*)&As[k][ty * 8 + 4];
            float4 b0 = *(const float4*)&Bs[k][tx * 8];
            float4 b1 = *(const float4*)&Bs[k][tx * 8 + 4];
            float av[8] = {a0.x, a0.y, a0.z, a0.w, a1.x, a1.y, a1.z, a1.w};
            float bv[8] = {b0.x, b0.y, b0.z, b0.w, b1.x, b1.y, b1.z, b1.w};
#pragma unroll
            for (int i = 0; i < 8; i++)
#pragma unroll
                for (int j = 0; j < 8; j++) acc[i][j] += av[i] * bv[j];
        }
        __syncthreads();
    }

#pragma unroll
    for (int i = 0; i < 8; i++) {
        int gm = bm + ty * 8 + i;
        if (gm >= M) break;
#pragma unroll
        for (int jq = 0; jq < 2; jq++) {
            int gc = bn + tx * 8 + jq * 4;
            float4 o;
            o.x = acc[i][jq * 4 + 0] + bias[gc + 0];
            o.y = acc[i][jq * 4 + 1] + bias[gc + 1];
            o.z = acc[i][jq * 4 + 2] + bias[gc + 2];
            o.w = acc[i][jq * 4 + 3] + bias[gc + 3];
            *(float4*)&C[(size_t)gm * N + gc] = o;
        }
    }
}

// ---------------------------------------------------------------------------
// Recurrence GEMM: partials of  h[64,512] @ W_hh[2048,512]^T
// grid = (32 n-tiles of 64, 4 k-splits of 128). 256 threads, 4x4 microtile.
// Writes g_part[ksplit][batch][gatecol].
// ---------------------------------------------------------------------------
__global__ void __launch_bounds__(256, 4)
lstm_hgemm(const float* __restrict__ W_hh) {
    __shared__ float Hs[32][72];
    __shared__ float Ws[32][72];
    const int tid = threadIdx.x;
    const int n0 = blockIdx.x * 64;
    const int k0 = blockIdx.y * 128;
    const int tx = tid & 15;
    const int ty = tid >> 4;

    float acc[4][4];
#pragma unroll
    for (int i = 0; i < 4; i++)
#pragma unroll
        for (int j = 0; j < 4; j++) acc[i][j] = 0.f;

    for (int kk = 0; kk < 128; kk += 32) {
#pragma unroll
        for (int i = 0; i < 2; i++) {
            int idx = tid + 256 * i;
            int row = idx >> 3;    // 0..63
            int c4  = idx & 7;     // 0..7
            float4 v = *(const float4*)&g_h[row * HDIM + k0 + kk + c4 * 4];
            Hs[c4 * 4 + 0][row] = v.x;
            Hs[c4 * 4 + 1][row] = v.y;
            Hs[c4 * 4 + 2][row] = v.z;
            Hs[c4 * 4 + 3][row] = v.w;
            float4 w = *(const float4*)&W_hh[(size_t)(n0 + row) * HDIM + k0 + kk + c4 * 4];
            Ws[c4 * 4 + 0][row] = w.x;
            Ws[c4 * 4 + 1][row] = w.y;
            Ws[c4 * 4 + 2][row] = w.z;
            Ws[c4 * 4 + 3][row] = w.w;
        }
        __syncthreads();
#pragma unroll
        for (int k = 0; k < 32; k++) {
            float4 a = *(const float4*)&Hs[k][ty * 4];
            float4 b = *(const float4*)&Ws[k][tx * 4];
            float av[4] = {a.x, a.y, a.z, a.w};
            float bv[4] = {b.x, b.y, b.z, b.w};
#pragma unroll
            for (int i = 0; i < 4; i++)
#pragma unroll
                for (int j = 0; j < 4; j++) acc[i][j] += av[i] * bv[j];
        }
        __syncthreads();
    }

    float* outp = &g_part[((size_t)blockIdx.y * BATCH + ty * 4) * GDIM + n0 + tx * 4];
#pragma unroll
    for (int i = 0; i < 4; i++) {
        float4 o = make_float4(acc[i][0], acc[i][1], acc[i][2], acc[i][3]);
        *(float4*)&outp[(size_t)i * GDIM] = o;
    }
}

// ---------------------------------------------------------------------------
// LSTM cell: gates = G[t] + sum_k g_part[k]; update h, c; stash decoder h.
// ---------------------------------------------------------------------------
__device__ __forceinline__ float sigmoidf_(float x) {
    return 1.f / (1.f + expf(-x));
}

__global__ void lstm_cell(int t) {
    int idx = blockIdx.x * blockDim.x + threadIdx.x;  // 0 .. 64*512-1
    int b = idx >> 9;
    int j = idx & 511;
    const float* G = &g_G[((size_t)t * BATCH + b) * GDIM];
    float gi = G[j];
    float gf = G[512 + j];
    float gg = G[1024 + j];
    float go = G[1536 + j];
#pragma unroll
    for (int ks = 0; ks < 4; ks++) {
        const float* P = &g_part[((size_t)ks * BATCH + b) * GDIM];
        gi += P[j];
        gf += P[512 + j];
        gg += P[1024 + j];
        go += P[1536 + j];
    }
    float c = g_c[idx];
    float cn = sigmoidf_(gf) * c + sigmoidf_(gi) * tanhf(gg);
    float hn = sigmoidf_(go) * tanhf(cn);
    g_c[idx] = cn;
    g_h[idx] = hn;
    if (t >= MAXFRAME && t < MAXFRAME + CAPLEN - 1) {
        g_dech[((size_t)b * (CAPLEN - 1) + (t - MAXFRAME)) * HDIM + j] = hn;
    }
}

// ---------------------------------------------------------------------------
// launch
// ---------------------------------------------------------------------------
extern "C" void kernel_launch(void* const* d_in, const int* in_sizes, int n_in,
                              void* d_out, int out_size) {
    const float* feature   = (const float*)d_in[0];
    const int*   captions  = (const int*)d_in[1];
    const float* embedding = (const float*)d_in[2];
    const float* W_ih      = (const float*)d_in[3];
    const float* W_hh      = (const float*)d_in[4];
    const float* b_ih      = (const float*)d_in[5];
    const float* b_hh      = (const float*)d_in[6];
    const float* W_lin     = (const float*)d_in[7];
    const float* b_lin     = (const float*)d_in[8];
    float* out = (float*)d_out;

    void *pX, *pG, *pBias, *pDecH;
    cudaGetSymbolAddress(&pX, g_X);
    cudaGetSymbolAddress(&pG, g_G);
    cudaGetSymbolAddress(&pBias, g_bias);
    cudaGetSymbolAddress(&pDecH, g_dech);

    // 1) materialize xs
    build_x_kernel<<<3840, 256>>>(feature, captions, embedding);
    // 2) zero state + combined bias
    prep_kernel<<<128, 256>>>(b_ih, b_hh);
    // 3) all input-side gates in one GEMM: [3840,1024] x [1024,2048]^T
    sgemm_nt<<<dim3(GDIM / 128, (TSTEPS * BATCH) / 128), 256>>>(
        (const float*)pX, W_ih, (const float*)pBias, (float*)pG,
        TSTEPS * BATCH, GDIM, XDIM);
    // 4) sequential recurrence: 60 x (h-GEMM + cell)
    for (int t = 0; t < TSTEPS; t++) {
        lstm_hgemm<<<dim3(32, 4), 256>>>(W_hh);
        lstm_cell<<<64, 512>>>(t);
    }
    // 5) projection: [1216,512] x [512,32000]^T + b_lin
    sgemm_nt<<<dim3(VOCAB / 128, (OUTROWS + 127) / 128), 256>>>(
        (const float*)pDecH, W_lin, b_lin, out,
        OUTROWS, VOCAB, HDIM);
}

// round 4
// speedup vs baseline: 1.9640x; 1.9636x over previous
#include <cuda_runtime.h>
#include <math.h>
#include <stdint.h>

#define BATCH 64
#define TSTEPS 60
#define MAXFRAME 40
#define CAPLEN 20
#define HDIM 512
#define XDIM 1024
#define GDIM 2048
#define VOCAB 32000
#define OUTROWS 1216
#define OUTROWS_PAD 1280

// ---------------- device scratch ----------------
__device__ float g_X[TSTEPS * BATCH * XDIM];
__device__ float g_G[TSTEPS * BATCH * GDIM];
__device__ float g_bias[GDIM];
__device__ float g_hT[2][HDIM * BATCH];     // transposed h: [k][b]
__device__ float g_dech[OUTROWS_PAD * HDIM];
__device__ unsigned g_bar_count;
__device__ volatile unsigned g_bar_gen;

// ---------------- build xs ----------------
__global__ void build_x_kernel(const float* __restrict__ feature,
                               const int* __restrict__ captions,
                               const float* __restrict__ embedding) {
    int idx = blockIdx.x * blockDim.x + threadIdx.x;
    int r = idx >> 8, c4 = idx & 255;
    int t = r >> 6, b = r & 63;
    float4 v = make_float4(0.f, 0.f, 0.f, 0.f);
    if (c4 < 128) {
        if (t >= MAXFRAME) {
            int cap = captions[b * CAPLEN + (t - MAXFRAME)];
            v = *(const float4*)&embedding[(size_t)cap * HDIM + c4 * 4];
        }
    } else {
        v = *(const float4*)&feature[((size_t)b * TSTEPS + t) * HDIM + (c4 - 128) * 4];
    }
    *(float4*)&g_X[(size_t)r * XDIM + c4 * 4] = v;
}

// ---------------- prep ----------------
__global__ void prep_kernel(const float* __restrict__ b_ih, const float* __restrict__ b_hh) {
    int idx = blockIdx.x * blockDim.x + threadIdx.x;
    if (idx < 2 * HDIM * BATCH) ((float*)g_hT)[idx] = 0.f;
    if (idx < GDIM) g_bias[idx] = b_ih[idx] + b_hh[idx];
    if (idx == 0) { g_bar_count = 0; g_bar_gen = 0; }
}

// ---------------- tf32 helpers ----------------
__device__ __forceinline__ uint32_t to_tf32(float f) {
    uint32_t r;
    asm("cvt.rna.tf32.f32 %0, %1;" : "=r"(r) : "f"(f));
    return r;
}
__device__ __forceinline__ void mma_tf32_16x8x8(float* c, const uint32_t* a, const uint32_t* b) {
    asm volatile(
        "mma.sync.aligned.m16n8k8.row.col.f32.tf32.tf32.f32 "
        "{%0,%1,%2,%3}, {%4,%5,%6,%7}, {%8,%9}, {%0,%1,%2,%3};"
        : "+f"(c[0]), "+f"(c[1]), "+f"(c[2]), "+f"(c[3])
        : "r"(a[0]), "r"(a[1]), "r"(a[2]), "r"(a[3]), "r"(b[0]), "r"(b[1]));
}

// ---------------- tf32 mma.sync GEMM ----------------
// C[M,N] = A[M,K] * B[N,K]^T + bias[N].  Block 128x128, BK=32, 256 thr.
// Warps: 4(M) x 2(N); warp tile 32x64; mma m16n8k8.
// dyn smem: sA[2][128][36], sB[2][128][36] floats = 73728 bytes.
#define GEMM_SMEM 73728

__global__ void __launch_bounds__(256, 1)
tf32_gemm(const float* __restrict__ A, const float* __restrict__ B,
          const float* __restrict__ bias, float* __restrict__ C,
          int M, int N, int K) {
    extern __shared__ float sm[];
    float* sA0 = sm;            // 4608 floats each
    float* sA1 = sm + 4608;
    float* sB0 = sm + 9216;
    float* sB1 = sm + 13824;

    const int tid = threadIdx.x;
    const int lane = tid & 31, wid = tid >> 5;
    const int wm = wid & 3, wn = wid >> 2;
    const int g = lane >> 2, tig = lane & 3;
    const int bm = blockIdx.y * 128, bn = blockIdx.x * 128;

    const int ldrow = tid >> 3;     // base row for this thread's 1st of 4 loads
    const int ldc4  = tid & 7;

    float acc[2][8][4];
#pragma unroll
    for (int mf = 0; mf < 2; mf++)
#pragma unroll
        for (int nf = 0; nf < 8; nf++)
#pragma unroll
            for (int i = 0; i < 4; i++) acc[mf][nf][i] = 0.f;

    const int NC = K >> 5;

    // ---- load chunk 0 ----
#pragma unroll
    for (int i = 0; i < 4; i++) {
        int row = ldrow + (i << 5);
        float4 va = *(const float4*)&A[(size_t)(bm + row) * K + (ldc4 << 2)];
        float4 vb = *(const float4*)&B[(size_t)(bn + row) * K + (ldc4 << 2)];
        float* pA = &sA0[row * 36 + (ldc4 << 2)];
        float* pB = &sB0[row * 36 + (ldc4 << 2)];
        pA[0] = __uint_as_float(to_tf32(va.x)); pA[1] = __uint_as_float(to_tf32(va.y));
        pA[2] = __uint_as_float(to_tf32(va.z)); pA[3] = __uint_as_float(to_tf32(va.w));
        pB[0] = __uint_as_float(to_tf32(vb.x)); pB[1] = __uint_as_float(to_tf32(vb.y));
        pB[2] = __uint_as_float(to_tf32(vb.z)); pB[3] = __uint_as_float(to_tf32(vb.w));
    }
    __syncthreads();

    float4 pa[4], pb[4];
    for (int c = 0; c < NC; c++) {
        const float* cA = (c & 1) ? sA1 : sA0;
        const float* cB = (c & 1) ? sB1 : sB0;

        if (c + 1 < NC) {
            const int k0 = (c + 1) << 5;
#pragma unroll
            for (int i = 0; i < 4; i++) {
                int row = ldrow + (i << 5);
                pa[i] = *(const float4*)&A[(size_t)(bm + row) * K + k0 + (ldc4 << 2)];
                pb[i] = *(const float4*)&B[(size_t)(bn + row) * K + k0 + (ldc4 << 2)];
            }
        }

#pragma unroll
        for (int ks = 0; ks < 4; ks++) {
            const int acol = (ks << 3) + tig;
            uint32_t af[2][4], bf[8][2];
#pragma unroll
            for (int mf = 0; mf < 2; mf++) {
                int r0 = wm * 32 + mf * 16 + g;
                af[mf][0] = __float_as_uint(cA[r0 * 36 + acol]);
                af[mf][1] = __float_as_uint(cA[(r0 + 8) * 36 + acol]);
                af[mf][2] = __float_as_uint(cA[r0 * 36 + acol + 4]);
                af[mf][3] = __float_as_uint(cA[(r0 + 8) * 36 + acol + 4]);
            }
#pragma unroll
            for (int nf = 0; nf < 8; nf++) {
                int n = wn * 64 + nf * 8 + g;
                bf[nf][0] = __float_as_uint(cB[n * 36 + acol]);
                bf[nf][1] = __float_as_uint(cB[n * 36 + acol + 4]);
            }
#pragma unroll
            for (int mf = 0; mf < 2; mf++)
#pragma unroll
                for (int nf = 0; nf < 8; nf++)
                    mma_tf32_16x8x8(acc[mf][nf], af[mf], bf[nf]);
        }

        if (c + 1 < NC) {
            float* nA = (c & 1) ? sA0 : sA1;
            float* nB = (c & 1) ? sB0 : sB1;
#pragma unroll
            for (int i = 0; i < 4; i++) {
                int row = ldrow + (i << 5);
                float* pA = &nA[row * 36 + (ldc4 << 2)];
                float* pB = &nB[row * 36 + (ldc4 << 2)];
                pA[0] = __uint_as_float(to_tf32(pa[i].x)); pA[1] = __uint_as_float(to_tf32(pa[i].y));
                pA[2] = __uint_as_float(to_tf32(pa[i].z)); pA[3] = __uint_as_float(to_tf32(pa[i].w));
                pB[0] = __uint_as_float(to_tf32(pb[i].x)); pB[1] = __uint_as_float(to_tf32(pb[i].y));
                pB[2] = __uint_as_float(to_tf32(pb[i].z)); pB[3] = __uint_as_float(to_tf32(pb[i].w));
            }
            __syncthreads();
        }
    }

    // ---- epilogue: direct stores (+bias), row-guarded ----
#pragma unroll
    for (int mf = 0; mf < 2; mf++) {
        int r0 = bm + wm * 32 + mf * 16 + g;
#pragma unroll
        for (int nf = 0; nf < 8; nf++) {
            int col = bn + wn * 64 + nf * 8 + (tig << 1);
            float b0 = bias[col], b1 = bias[col + 1];
            if (r0 < M) {
                float2 v = make_float2(acc[mf][nf][0] + b0, acc[mf][nf][1] + b1);
                *(float2*)&C[(size_t)r0 * N + col] = v;
            }
            if (r0 + 8 < M) {
                float2 v = make_float2(acc[mf][nf][2] + b0, acc[mf][nf][3] + b1);
                *(float2*)&C[(size_t)(r0 + 8) * N + col] = v;
            }
        }
    }
}

// ---------------- persistent LSTM recurrence ----------------
// 128 CTAs x 256 thr. CTA cc owns hidden cols j0=cc*4..cc*4+3 (16 gate rows).
#define HS_OFF 0
#define WS_OFF 139264
#define RED_OFF 172032
#define RED2_OFF 188416
#define LSTM_SMEM 192512

__device__ __forceinline__ float sigf(float x) { return 1.f / (1.f + __expf(-x)); }

__device__ __forceinline__ void grid_sync_() {
    __syncthreads();
    if (threadIdx.x == 0) {
        __threadfence();
        unsigned gen = g_bar_gen;
        if (atomicAdd(&g_bar_count, 1u) == (unsigned)(gridDim.x - 1)) {
            g_bar_count = 0;
            __threadfence();
            g_bar_gen = gen + 1;
        } else {
            while (g_bar_gen == gen) { __nanosleep(64); }
        }
        __threadfence();
    }
    __syncthreads();
}

__global__ void __launch_bounds__(256, 1)
lstm_persistent(const float* __restrict__ W_hh) {
    extern __shared__ char smem[];
    float* hs   = (float*)(smem + HS_OFF);    // [512][68], f4-col swizzled (*5 mod 16)
    float* ws   = (float*)(smem + WS_OFF);    // ws[kk*16 + r], r = gate*4 + cl
    float* red  = (float*)(smem + RED_OFF);   // [4][1024]
    float* red2 = (float*)(smem + RED2_OFF);  // [16][64]

    const int tid = threadIdx.x;
    const int j0 = blockIdx.x * 4;
    const int sq = tid >> 6;                 // K slice (0..3)
    const int cq = (tid >> 4) & 3;           // gate (0..3)
    const int bq = tid & 15;                 // batch quad
    const int hcol = ((bq * 5) & 15) << 2;
    const int cl = tid >> 6;                 // cell: local col
    const int b  = tid & 63;                 // cell: batch

    // load weights once: ws[kk*16 + gate*4+cl] = W_hh[(gate*512 + j0+cl)*512 + kk]
#pragma unroll
    for (int i = 0; i < 32; i++) {
        int idx = tid + (i << 8);
        int r = idx >> 9, kk = idx & 511;
        int wrow = ((r >> 2) << 9) + j0 + (r & 3);
        ws[kk * 16 + r] = W_hh[(size_t)wrow * HDIM + kk];
    }

    float c_reg = 0.f;
    grid_sync_();

    for (int t = 0; t < TSTEPS; t++) {
        const float* Gt = &g_G[((size_t)t * BATCH + b) * GDIM + j0 + cl];
        float gI = __ldg(Gt);
        float gF = __ldg(Gt + 512);
        float gG = __ldg(Gt + 1024);
        float gO = __ldg(Gt + 1536);

        const float* hsrc = g_hT[t & 1];
#pragma unroll
        for (int i = 0; i < 32; i++) {
            int idx = tid + (i << 8);
            int row = idx >> 4, c4 = idx & 15;
            float4 v = __ldcg((const float4*)&hsrc[row * 64 + c4 * 4]);
            *(float4*)&hs[row * 68 + (((c4 * 5) & 15) << 2)] = v;
        }
        __syncthreads();

        float acc[4][4];
#pragma unroll
        for (int i = 0; i < 4; i++)
#pragma unroll
            for (int j = 0; j < 4; j++) acc[i][j] = 0.f;
        const int kbase = sq << 7;
#pragma unroll 4
        for (int k = 0; k < 128; k++) {
            int kk = kbase + k;
            float4 wv = *(const float4*)&ws[kk * 16 + (cq << 2)];
            float4 hv = *(const float4*)&hs[kk * 68 + hcol];
            acc[0][0] += wv.x * hv.x; acc[0][1] += wv.x * hv.y; acc[0][2] += wv.x * hv.z; acc[0][3] += wv.x * hv.w;
            acc[1][0] += wv.y * hv.x; acc[1][1] += wv.y * hv.y; acc[1][2] += wv.y * hv.z; acc[1][3] += wv.y * hv.w;
            acc[2][0] += wv.z * hv.x; acc[2][1] += wv.z * hv.y; acc[2][2] += wv.z * hv.z; acc[2][3] += wv.z * hv.w;
            acc[3][0] += wv.w * hv.x; acc[3][1] += wv.w * hv.y; acc[3][2] += wv.w * hv.z; acc[3][3] += wv.w * hv.w;
        }
#pragma unroll
        for (int r = 0; r < 4; r++) {
            float4 o = make_float4(acc[r][0], acc[r][1], acc[r][2], acc[r][3]);
            *(float4*)&red[sq * 1024 + ((cq * 4 + r) << 6) + (bq << 2)] = o;
        }
        __syncthreads();
        {
            float4 s0 = ((const float4*)red)[tid];
            float4 s1 = ((const float4*)red)[256 + tid];
            float4 s2 = ((const float4*)red)[512 + tid];
            float4 s3 = ((const float4*)red)[768 + tid];
            float4 o;
            o.x = s0.x + s1.x + s2.x + s3.x;
            o.y = s0.y + s1.y + s2.y + s3.y;
            o.z = s0.z + s1.z + s2.z + s3.z;
            o.w = s0.w + s1.w + s2.w + s3.w;
            ((float4*)red2)[tid] = o;
        }
        __syncthreads();
        {
            float xi = gI + red2[(0  + cl) * 64 + b];
            float xf = gF + red2[(4  + cl) * 64 + b];
            float xg = gG + red2[(8  + cl) * 64 + b];
            float xo = gO + red2[(12 + cl) * 64 + b];
            float cn = sigf(xf) * c_reg + sigf(xi) * tanhf(xg);
            float hn = sigf(xo) * tanhf(cn);
            c_reg = cn;
            g_hT[(t + 1) & 1][(j0 + cl) * 64 + b] = hn;
            if (t >= MAXFRAME && t < MAXFRAME + CAPLEN - 1) {
                g_dech[((size_t)b * (CAPLEN - 1) + (t - MAXFRAME)) * HDIM + j0 + cl] = hn;
            }
        }
        grid_sync_();
    }
}

// ---------------- launch ----------------
extern "C" void kernel_launch(void* const* d_in, const int* in_sizes, int n_in,
                              void* d_out, int out_size) {
    const float* feature   = (const float*)d_in[0];
    const int*   captions  = (const int*)d_in[1];
    const float* embedding = (const float*)d_in[2];
    const float* W_ih      = (const float*)d_in[3];
    const float* W_hh      = (const float*)d_in[4];
    const float* b_ih      = (const float*)d_in[5];
    const float* b_hh      = (const float*)d_in[6];
    const float* W_lin     = (const float*)d_in[7];
    const float* b_lin     = (const float*)d_in[8];
    float* out = (float*)d_out;

    cudaFuncSetAttribute(tf32_gemm, cudaFuncAttributeMaxDynamicSharedMemorySize, GEMM_SMEM);
    cudaFuncSetAttribute(lstm_persistent, cudaFuncAttributeMaxDynamicSharedMemorySize, LSTM_SMEM);

    void *pX, *pG, *pBias, *pDecH;
    cudaGetSymbolAddress(&pX, g_X);
    cudaGetSymbolAddress(&pG, g_G);
    cudaGetSymbolAddress(&pBias, g_bias);
    cudaGetSymbolAddress(&pDecH, g_dech);

    build_x_kernel<<<3840, 256>>>(feature, captions, embedding);
    prep_kernel<<<256, 256>>>(b_ih, b_hh);
    // gate precompute: [3840,1024] x [1024,2048]^T + bias
    tf32_gemm<<<dim3(GDIM / 128, (TSTEPS * BATCH) / 128), 256, GEMM_SMEM>>>(
        (const float*)pX, W_ih, (const float*)pBias, (float*)pG,
        TSTEPS * BATCH, GDIM, XDIM);
    // recurrence (persistent, 128 CTAs)
    lstm_persistent<<<128, 256, LSTM_SMEM>>>(W_hh);
    // projection: [1280,512] x [512,32000]^T + b_lin (stores guarded to 1216)
    tf32_gemm<<<dim3(VOCAB / 128, OUTROWS_PAD / 128), 256, GEMM_SMEM>>>(
        (const float*)pDecH, W_lin, b_lin, out,
        OUTROWS, VOCAB, HDIM);
}

// round 5
// speedup vs baseline: 2.8279x; 1.4398x over previous
#include <cuda_runtime.h>
#include <cuda_fp16.h>
#include <math.h>
#include <stdint.h>

#define BATCH 64
#define TSTEPS 60
#define MAXFRAME 40
#define CAPLEN 20
#define HDIM 512
#define XDIM 1024
#define GDIM 2048
#define VOCAB 32000
#define OUTROWS 1216
#define OUTROWS_PAD 1280

// ---------------- device scratch ----------------
__device__ __half g_Xh[TSTEPS * BATCH * XDIM];     // fp16 xs
__device__ float  g_G[TSTEPS * BATCH * GDIM];      // fp32 x-side gates + bias
__device__ float  g_bias[GDIM];
__device__ __half g_WihH[GDIM * XDIM];
__device__ __half g_WlinH[VOCAB * HDIM];
__device__ __half g_hH[2][BATCH * HDIM];           // fp16 h double buffer [b][k]
__device__ __half g_dechH[OUTROWS_PAD * HDIM];     // fp16 decoder hiddens
__device__ unsigned g_cnt[TSTEPS];                 // per-step arrival counters

// ---------------- helpers ----------------
__device__ __forceinline__ uint32_t f2h2(float a, float b) {
    __half2 h = __floats2half2_rn(a, b);
    return *(uint32_t*)&h;
}
__device__ __forceinline__ void mma_h16(float* c, const uint32_t* a, const uint32_t* b) {
    asm volatile(
        "mma.sync.aligned.m16n8k16.row.col.f32.f16.f16.f32 "
        "{%0,%1,%2,%3}, {%4,%5,%6,%7}, {%8,%9}, {%0,%1,%2,%3};"
        : "+f"(c[0]), "+f"(c[1]), "+f"(c[2]), "+f"(c[3])
        : "r"(a[0]), "r"(a[1]), "r"(a[2]), "r"(a[3]), "r"(b[0]), "r"(b[1]));
}
__device__ __forceinline__ float sigf(float x) { return 1.f / (1.f + __expf(-x)); }

// ---------------- build xs (fp16) ----------------
__global__ void build_xh(const float* __restrict__ feature,
                         const int* __restrict__ captions,
                         const float* __restrict__ embedding) {
    int idx = blockIdx.x * 256 + threadIdx.x;      // uint4 index: 3840*128
    int r = idx >> 7, c8 = idx & 127;
    int t = r >> 6, b = r & 63;
    float4 lo = make_float4(0.f, 0.f, 0.f, 0.f), hi = lo;
    if (c8 < 64) {
        if (t >= MAXFRAME) {
            int cap = captions[b * CAPLEN + (t - MAXFRAME)];
            const float4* src = (const float4*)&embedding[(size_t)cap * HDIM + c8 * 8];
            lo = src[0]; hi = src[1];
        }
    } else {
        const float4* src = (const float4*)&feature[((size_t)b * TSTEPS + t) * HDIM + (c8 - 64) * 8];
        lo = src[0]; hi = src[1];
    }
    uint4 o;
    o.x = f2h2(lo.x, lo.y); o.y = f2h2(lo.z, lo.w);
    o.z = f2h2(hi.x, hi.y); o.w = f2h2(hi.z, hi.w);
    ((uint4*)g_Xh)[idx] = o;
}

// ---------------- fp32 -> fp16 convert (8 elems / thread) ----------------
__global__ void conv_h(const float* __restrict__ s, __half* __restrict__ d, int n8) {
    int i = blockIdx.x * 256 + threadIdx.x;
    if (i < n8) {
        float4 a = ((const float4*)s)[i * 2];
        float4 b = ((const float4*)s)[i * 2 + 1];
        uint4 o;
        o.x = f2h2(a.x, a.y); o.y = f2h2(a.z, a.w);
        o.z = f2h2(b.x, b.y); o.w = f2h2(b.z, b.w);
        ((uint4*)d)[i] = o;
    }
}

// ---------------- prep ----------------
__global__ void prep_kernel(const float* __restrict__ b_ih, const float* __restrict__ b_hh) {
    int idx = blockIdx.x * 256 + threadIdx.x;      // 16384 threads
    ((uint32_t*)g_hH)[idx] = 0u;                   // zero h buffer 0 (64*512 halves)
    ((uint32_t*)g_dechH)[OUTROWS * HDIM / 2 + idx & 0x7FFFFFFF] = 0u; // placeholder (fixed below)
    if (idx < (OUTROWS_PAD - OUTROWS) * HDIM / 2)
        ((uint32_t*)g_dechH)[OUTROWS * HDIM / 2 + idx] = 0u;          // zero pad rows
    if (idx < GDIM) g_bias[idx] = b_ih[idx] + b_hh[idx];
    if (idx < TSTEPS) g_cnt[idx] = 0u;
}

// ---------------- fp16 mma GEMM: C[M,N] = A[M,K]*B[N,K]^T + bias[N] ----------------
// Block 128x128, BK=32, 256 thr, warps 4(M)x2(N), warp tile 32x64, m16n8k16.
#define GP 40                                       // smem pitch (halves)
#define GEMM_SMEM (4 * 128 * GP * 2)                // 40960 B

__global__ void __launch_bounds__(256)
h16_gemm(const __half* __restrict__ A, const __half* __restrict__ B,
         const float* __restrict__ bias, float* __restrict__ C,
         int M, int N, int K) {
    extern __shared__ __half sh[];
    __half* sA = sh;                                // [2][128][GP]
    __half* sB = sh + 2 * 128 * GP;

    const int tid = threadIdx.x, lane = tid & 31, wid = tid >> 5;
    const int wm = wid & 3, wn = wid >> 2;
    const int g = lane >> 2, tig = lane & 3;
    const int bm = blockIdx.y * 128, bn = blockIdx.x * 128;
    const int frow = tid >> 1, fseg = tid & 1;

    float acc[2][8][4];
#pragma unroll
    for (int mi = 0; mi < 2; mi++)
#pragma unroll
        for (int nj = 0; nj < 8; nj++)
#pragma unroll
            for (int i = 0; i < 4; i++) acc[mi][nj][i] = 0.f;

    const int NC = K >> 5;
    {   // fill chunk 0
        const uint4* pa = (const uint4*)&A[(size_t)(bm + frow) * K + fseg * 16];
        const uint4* pb = (const uint4*)&B[(size_t)(bn + frow) * K + fseg * 16];
        uint4 a0 = pa[0], a1 = pa[1], b0 = pb[0], b1 = pb[1];
        *(uint4*)&sA[frow * GP + fseg * 16] = a0;
        *(uint4*)&sA[frow * GP + fseg * 16 + 8] = a1;
        *(uint4*)&sB[frow * GP + fseg * 16] = b0;
        *(uint4*)&sB[frow * GP + fseg * 16 + 8] = b1;
    }
    __syncthreads();

    uint4 pfa0, pfa1, pfb0, pfb1;
    for (int c = 0; c < NC; c++) {
        const __half* cA = sA + (c & 1) * 128 * GP;
        const __half* cB = sB + (c & 1) * 128 * GP;
        if (c + 1 < NC) {
            int k0 = (c + 1) << 5;
            const uint4* pa = (const uint4*)&A[(size_t)(bm + frow) * K + k0 + fseg * 16];
            const uint4* pb = (const uint4*)&B[(size_t)(bn + frow) * K + k0 + fseg * 16];
            pfa0 = pa[0]; pfa1 = pa[1]; pfb0 = pb[0]; pfb1 = pb[1];
        }
#pragma unroll
        for (int kk = 0; kk < 2; kk++) {
            const int kb = kk * 16 + tig * 2;
            uint32_t af[2][4], bf[8][2];
#pragma unroll
            for (int mi = 0; mi < 2; mi++) {
                const __half* base = &cA[(wm * 32 + mi * 16 + g) * GP + kb];
                af[mi][0] = *(const uint32_t*)(base);
                af[mi][1] = *(const uint32_t*)(base + 8 * GP);
                af[mi][2] = *(const uint32_t*)(base + 8);
                af[mi][3] = *(const uint32_t*)(base + 8 * GP + 8);
            }
#pragma unroll
            for (int nj = 0; nj < 8; nj++) {
                const __half* nb = &cB[(wn * 64 + nj * 8 + g) * GP + kb];
                bf[nj][0] = *(const uint32_t*)(nb);
                bf[nj][1] = *(const uint32_t*)(nb + 8);
            }
#pragma unroll
            for (int mi = 0; mi < 2; mi++)
#pragma unroll
                for (int nj = 0; nj < 8; nj++)
                    mma_h16(acc[mi][nj], af[mi], bf[nj]);
        }
        if (c + 1 < NC) {
            __half* nA = sA + ((c + 1) & 1) * 128 * GP;
            __half* nB = sB + ((c + 1) & 1) * 128 * GP;
            *(uint4*)&nA[frow * GP + fseg * 16] = pfa0;
            *(uint4*)&nA[frow * GP + fseg * 16 + 8] = pfa1;
            *(uint4*)&nB[frow * GP + fseg * 16] = pfb0;
            *(uint4*)&nB[frow * GP + fseg * 16 + 8] = pfb1;
            __syncthreads();
        }
    }

#pragma unroll
    for (int mi = 0; mi < 2; mi++) {
        int r0 = bm + wm * 32 + mi * 16 + g;
#pragma unroll
        for (int nj = 0; nj < 8; nj++) {
            int col = bn + wn * 64 + nj * 8 + tig * 2;
            float b0 = bias[col], b1 = bias[col + 1];
            if (r0 < M) {
                float2 v = make_float2(acc[mi][nj][0] + b0, acc[mi][nj][1] + b1);
                *(float2*)&C[(size_t)r0 * N + col] = v;
            }
            if (r0 + 8 < M) {
                float2 v = make_float2(acc[mi][nj][2] + b0, acc[mi][nj][3] + b1);
                *(float2*)&C[(size_t)(r0 + 8) * N + col] = v;
            }
        }
    }
}

// ---------------- persistent LSTM recurrence (fp16 mma) ----------------
// 128 CTAs x 256 thr. CTA owns 16 gate rows (4 hidden cols x 4 gates), kept as
// stationary B-fragments in registers. Warps split K (8 x 64). One-sided
// per-step counter replaces the grid barrier.
#define HP 520
#define RP 133
#define LSTM_SMEM ((16 + 64) * HP * 2 + 64 * RP * 4)   // 83200 + 34048 = 117248

__global__ void __launch_bounds__(256, 1)
lstm_mma(const float* __restrict__ W_hh) {
    extern __shared__ char sm8[];
    __half* wsh = (__half*)sm8;                    // [16][HP]
    __half* hsh = (__half*)(sm8 + 16 * HP * 2);    // [64][HP]
    float*  red = (float*)(sm8 + (16 + 64) * HP * 2);  // [64][RP]

    const int tid = threadIdx.x, lane = tid & 31, wid = tid >> 5;
    const int g = lane >> 2, tig = lane & 3;
    const int j0 = blockIdx.x * 4;
    const int kw = wid * 64;
    // fill mapping
    const int fb = tid & 63, fch = tid >> 6;
    // cell mapping (coalesced G loads)
    const int cb = tid >> 2, cl = tid & 3;

    // convert W slice into smem: wsh[r][k] = W_hh[(gate*512 + j0 + cl')*512 + k], r = gate*4+cl'
#pragma unroll
    for (int i = 0; i < 32; i++) {
        int idx = tid + (i << 8);
        int r = idx >> 9, k = idx & 511;
        int wrow = ((r >> 2) << 9) + j0 + (r & 3);
        wsh[r * HP + k] = __float2half(W_hh[(size_t)wrow * HDIM + k]);
    }
    __syncthreads();

    // stationary B fragments
    uint32_t breg[2][4][2];
#pragma unroll
    for (int nj = 0; nj < 2; nj++)
#pragma unroll
        for (int kk = 0; kk < 4; kk++) {
            const __half* p = &wsh[(nj * 8 + g) * HP + kw + kk * 16 + tig * 2];
            breg[nj][kk][0] = *(const uint32_t*)p;
            breg[nj][kk][1] = *(const uint32_t*)(p + 8);
        }

    float c_reg = 0.f;
    for (int t = 0; t < TSTEPS; t++) {
        if (t > 0) {
            if (tid == 0) {
                volatile unsigned* p = &g_cnt[t - 1];
                while (*p < 128u) { __nanosleep(32); }
                __threadfence();
            }
            __syncthreads();
        }
        // prefetch this step's x-side gates (coalesced 16B groups)
        const float* Gt = &g_G[((size_t)t * BATCH + cb) * GDIM + j0 + cl];
        float gI = __ldg(Gt);
        float gF = __ldg(Gt + 512);
        float gG = __ldg(Gt + 1024);
        float gO = __ldg(Gt + 1536);

        // fill hsh (bypass L1 — produced by other SMs)
        const __half* hsrc = g_hH[t & 1];
#pragma unroll
        for (int i = 0; i < 16; i++) {
            uint4 v = __ldcg((const uint4*)&hsrc[fb * HDIM + fch * 128 + i * 8]);
            *(uint4*)&hsh[fb * HP + fch * 128 + i * 8] = v;
        }
        __syncthreads();

        // mma: warp computes 64(batch) x 16(gate) over its 64-K slice
        float acc[4][2][4];
#pragma unroll
        for (int mi = 0; mi < 4; mi++)
#pragma unroll
            for (int nj = 0; nj < 2; nj++)
#pragma unroll
                for (int i = 0; i < 4; i++) acc[mi][nj][i] = 0.f;
#pragma unroll
        for (int mi = 0; mi < 4; mi++) {
#pragma unroll
            for (int kk = 0; kk < 4; kk++) {
                const __half* base = &hsh[(mi * 16 + g) * HP + kw + kk * 16 + tig * 2];
                uint32_t a[4];
                a[0] = *(const uint32_t*)(base);
                a[1] = *(const uint32_t*)(base + 8 * HP);
                a[2] = *(const uint32_t*)(base + 8);
                a[3] = *(const uint32_t*)(base + 8 * HP + 8);
                mma_h16(acc[mi][0], a, breg[0][kk]);
                mma_h16(acc[mi][1], a, breg[1][kk]);
            }
        }
        // stage partials: red[m][wid*16 + n]
#pragma unroll
        for (int mi = 0; mi < 4; mi++)
#pragma unroll
            for (int nj = 0; nj < 2; nj++) {
                int m0 = mi * 16 + g, n0 = nj * 8 + tig * 2;
                float* rp = &red[m0 * RP + wid * 16 + n0];
                rp[0] = acc[mi][nj][0];
                rp[1] = acc[mi][nj][1];
                rp[8 * RP] = acc[mi][nj][2];
                rp[8 * RP + 1] = acc[mi][nj][3];
            }
        __syncthreads();

        // reduce 8 warp partials + cell update for (cb, cl)
        float s0 = 0.f, s1 = 0.f, s2 = 0.f, s3 = 0.f;
#pragma unroll
        for (int w = 0; w < 8; w++) {
            const float* rp = &red[cb * RP + w * 16 + cl];
            s0 += rp[0]; s1 += rp[4]; s2 += rp[8]; s3 += rp[12];
        }
        float xi = gI + s0, xf = gF + s1, xg = gG + s2, xo = gO + s3;
        float cn = sigf(xf) * c_reg + sigf(xi) * tanhf(xg);
        float hn = sigf(xo) * tanhf(cn);
        c_reg = cn;
        g_hH[(t + 1) & 1][cb * HDIM + j0 + cl] = __float2half(hn);
        if (t >= MAXFRAME && t < MAXFRAME + CAPLEN - 1)
            g_dechH[((size_t)cb * (CAPLEN - 1) + (t - MAXFRAME)) * HDIM + j0 + cl] = __float2half(hn);
        __threadfence();
        __syncthreads();
        if (tid == 0) atomicAdd(&g_cnt[t], 1u);
    }
}

// ---------------- launch ----------------
extern "C" void kernel_launch(void* const* d_in, const int* in_sizes, int n_in,
                              void* d_out, int out_size) {
    const float* feature   = (const float*)d_in[0];
    const int*   captions  = (const int*)d_in[1];
    const float* embedding = (const float*)d_in[2];
    const float* W_ih      = (const float*)d_in[3];
    const float* W_hh      = (const float*)d_in[4];
    const float* b_ih      = (const float*)d_in[5];
    const float* b_hh      = (const float*)d_in[6];
    const float* W_lin     = (const float*)d_in[7];
    const float* b_lin     = (const float*)d_in[8];
    float* out = (float*)d_out;

    cudaFuncSetAttribute(h16_gemm, cudaFuncAttributeMaxDynamicSharedMemorySize, GEMM_SMEM);
    cudaFuncSetAttribute(lstm_mma, cudaFuncAttributeMaxDynamicSharedMemorySize, LSTM_SMEM);

    void *pXh, *pG, *pBias, *pWih, *pWlin, *pDech;
    cudaGetSymbolAddress(&pXh, g_Xh);
    cudaGetSymbolAddress(&pG, g_G);
    cudaGetSymbolAddress(&pBias, g_bias);
    cudaGetSymbolAddress(&pWih, g_WihH);
    cudaGetSymbolAddress(&pWlin, g_WlinH);
    cudaGetSymbolAddress(&pDech, g_dechH);

    build_xh<<<1920, 256>>>(feature, captions, embedding);
    prep_kernel<<<64, 256>>>(b_ih, b_hh);
    conv_h<<<1024, 256>>>(W_ih, (__half*)pWih, GDIM * XDIM / 8);
    conv_h<<<8000, 256>>>(W_lin, (__half*)pWlin, VOCAB * HDIM / 8);
    // gate precompute: [3840,1024] x [1024,2048]^T + bias
    h16_gemm<<<dim3(GDIM / 128, (TSTEPS * BATCH) / 128), 256, GEMM_SMEM>>>(
        (const __half*)pXh, (const __half*)pWih, (const float*)pBias, (float*)pG,
        TSTEPS * BATCH, GDIM, XDIM);
    // recurrence (persistent, 128 CTAs, fp16 mma)
    lstm_mma<<<128, 256, LSTM_SMEM>>>(W_hh);
    // projection: [1280,512] x [512,32000]^T + b_lin (stores guarded to 1216)
    h16_gemm<<<dim3(VOCAB / 128, OUTROWS_PAD / 128), 256, GEMM_SMEM>>>(
        (const __half*)pDech, (const __half*)pWlin, b_lin, out,
        OUTROWS, VOCAB, HDIM);
}

// round 6
// speedup vs baseline: 3.1088x; 1.0994x over previous
#include <cuda_runtime.h>
#include <cuda_fp16.h>
#include <math.h>
#include <stdint.h>

#define BATCH 64
#define TSTEPS 60
#define MAXFRAME 40
#define CAPLEN 20
#define HDIM 512
#define XDIM 1024
#define GDIM 2048
#define VOCAB 32000
#define OUTROWS 1216
#define OUTROWS_PAD 1280

// ---------------- device scratch ----------------
__device__ __half g_Xh[TSTEPS * BATCH * XDIM];
__device__ float  g_G[TSTEPS * BATCH * GDIM];
__device__ float  g_bias[GDIM];
__device__ __half g_WihH[GDIM * XDIM];
__device__ __half g_WlinH[VOCAB * HDIM];
__device__ __half g_hH[2][BATCH * HDIM];
__device__ __half g_dechH[OUTROWS_PAD * HDIM];
__device__ unsigned g_cnt[TSTEPS];

// ---------------- helpers ----------------
__device__ __forceinline__ uint32_t f2h2(float a, float b) {
    __half2 h = __floats2half2_rn(a, b);
    return *(uint32_t*)&h;
}
__device__ __forceinline__ void mma_h16(float* c, const uint32_t* a, const uint32_t* b) {
    asm volatile(
        "mma.sync.aligned.m16n8k16.row.col.f32.f16.f16.f32 "
        "{%0,%1,%2,%3}, {%4,%5,%6,%7}, {%8,%9}, {%0,%1,%2,%3};"
        : "+f"(c[0]), "+f"(c[1]), "+f"(c[2]), "+f"(c[3])
        : "r"(a[0]), "r"(a[1]), "r"(a[2]), "r"(a[3]), "r"(b[0]), "r"(b[1]));
}
__device__ __forceinline__ float sigf(float x) { return 1.f / (1.f + __expf(-x)); }
__device__ __forceinline__ void cp16(uint32_t d, const void* s) {
    asm volatile("cp.async.cg.shared.global [%0], [%1], 16;" :: "r"(d), "l"(s));
}
#define CP_COMMIT() asm volatile("cp.async.commit_group;" ::: "memory")
#define CP_WAIT1()  asm volatile("cp.async.wait_group 1;" ::: "memory")
#define CP_WAIT0()  asm volatile("cp.async.wait_group 0;" ::: "memory")
#define LDSM4(r0, r1, r2, r3, a) \
    asm volatile("ldmatrix.sync.aligned.m8n8.x4.shared.b16 {%0,%1,%2,%3}, [%4];" \
        : "=r"(r0), "=r"(r1), "=r"(r2), "=r"(r3) : "r"(a))

// ---------------- build xs (fp16) ----------------
__global__ void build_xh(const float* __restrict__ feature,
                         const int* __restrict__ captions,
                         const float* __restrict__ embedding) {
    int idx = blockIdx.x * 256 + threadIdx.x;
    int r = idx >> 7, c8 = idx & 127;
    int t = r >> 6, b = r & 63;
    float4 lo = make_float4(0.f, 0.f, 0.f, 0.f), hi = lo;
    if (c8 < 64) {
        if (t >= MAXFRAME) {
            int cap = captions[b * CAPLEN + (t - MAXFRAME)];
            const float4* src = (const float4*)&embedding[(size_t)cap * HDIM + c8 * 8];
            lo = src[0]; hi = src[1];
        }
    } else {
        const float4* src = (const float4*)&feature[((size_t)b * TSTEPS + t) * HDIM + (c8 - 64) * 8];
        lo = src[0]; hi = src[1];
    }
    uint4 o;
    o.x = f2h2(lo.x, lo.y); o.y = f2h2(lo.z, lo.w);
    o.z = f2h2(hi.x, hi.y); o.w = f2h2(hi.z, hi.w);
    ((uint4*)g_Xh)[idx] = o;
}

// ---------------- fp32 -> fp16 convert ----------------
__global__ void conv_h(const float* __restrict__ s, __half* __restrict__ d, int n8) {
    int i = blockIdx.x * 256 + threadIdx.x;
    if (i < n8) {
        float4 a = ((const float4*)s)[i * 2];
        float4 b = ((const float4*)s)[i * 2 + 1];
        uint4 o;
        o.x = f2h2(a.x, a.y); o.y = f2h2(a.z, a.w);
        o.z = f2h2(b.x, b.y); o.w = f2h2(b.z, b.w);
        ((uint4*)d)[i] = o;
    }
}

// ---------------- prep ----------------
__global__ void prep_kernel(const float* __restrict__ b_ih, const float* __restrict__ b_hh) {
    int idx = blockIdx.x * 256 + threadIdx.x;      // 16384 threads
    ((uint32_t*)g_hH)[idx] = 0u;                   // zero h buffer 0
    ((uint32_t*)g_dechH)[OUTROWS * HDIM / 2 + idx] = 0u;  // zero pad rows (exactly 16384 u32)
    if (idx < GDIM) g_bias[idx] = b_ih[idx] + b_hh[idx];
    if (idx < TSTEPS) g_cnt[idx] = 0u;
}

// ---------------- fp16 mma GEMM (cp.async 3-stage + ldmatrix) ----------------
// C[M,N] = A[M,K]*B[N,K]^T + bias[N]. Block 128x128, BK=32, 256 thr,
// warps 4(M)x2(N), warp tile 32x64, m16n8k16.
#define GP 40                                       // smem pitch in halves (80 B)
#define STAGE_B (128 * GP * 2 * 2)                  // A+B per stage = 20480 B
#define GEMM_SMEM (3 * STAGE_B)                     // 61440 B

__global__ void __launch_bounds__(256)
h16_gemm(const __half* __restrict__ A, const __half* __restrict__ B,
         const float* __restrict__ bias, float* __restrict__ C,
         int M, int N, int K) {
    extern __shared__ __half sh[];
    uint32_t sbase;
    asm("{ .reg .u64 t; cvta.to.shared.u64 t, %1; cvt.u32.u64 %0, t; }" : "=r"(sbase) : "l"(sh));

    const int tid = threadIdx.x, lane = tid & 31, wid = tid >> 5;
    const int wm = wid & 3, wn = wid >> 2;
    const int g = lane >> 2, tig = lane & 3;
    const int bm = blockIdx.y * 128, bn = blockIdx.x * 128;

    // cp.async fill mapping: each thread copies 32B of A and 32B of B per stage
    const int frow = tid >> 1, fho = (tid & 1) * 16;  // row, half-offset in halves
    const __half* gA = &A[(size_t)(bm + frow) * K + fho];
    const __half* gB = &B[(size_t)(bn + frow) * K + fho];
    const uint32_t fsoff = (uint32_t)(frow * GP + fho) * 2;

    // ldmatrix per-lane offsets
    const int arow = wm * 32 + ((lane & 7) | (((lane >> 3) & 1) << 3));
    const int acol = (lane >> 4) * 8;
    const int brow = wn * 64 + (lane & 7) + ((lane >> 4) << 3);
    const int bcol = ((lane >> 3) & 1) * 8;

    float acc[2][8][4];
#pragma unroll
    for (int mi = 0; mi < 2; mi++)
#pragma unroll
        for (int nj = 0; nj < 8; nj++)
#pragma unroll
            for (int i = 0; i < 4; i++) acc[mi][nj][i] = 0.f;

    const int NC = K >> 5;

    // prologue: stages 0, 1
#pragma unroll
    for (int s = 0; s < 2; s++) {
        uint32_t sa = sbase + s * STAGE_B + fsoff;
        uint32_t sb = sa + 128 * GP * 2;
        const __half* pa = gA + (s << 5);
        const __half* pb = gB + (s << 5);
        cp16(sa, pa); cp16(sa + 16, pa + 8);
        cp16(sb, pb); cp16(sb + 16, pb + 8);
        CP_COMMIT();
    }
    CP_WAIT1();
    __syncthreads();

    for (int c = 0; c < NC; c++) {
        const int cur = c % 3;
        if (c + 2 < NC) {
            const int ns = (c + 2) % 3;
            uint32_t sa = sbase + ns * STAGE_B + fsoff;
            uint32_t sb = sa + 128 * GP * 2;
            const __half* pa = gA + ((c + 2) << 5);
            const __half* pb = gB + ((c + 2) << 5);
            cp16(sa, pa); cp16(sa + 16, pa + 8);
            cp16(sb, pb); cp16(sb + 16, pb + 8);
            CP_COMMIT();
        }
        const uint32_t sA = sbase + cur * STAGE_B;
        const uint32_t sB = sA + 128 * GP * 2;
#pragma unroll
        for (int kk = 0; kk < 2; kk++) {
            const int k0 = kk * 16;
            uint32_t af[2][4], bf[8][2];
#pragma unroll
            for (int mi = 0; mi < 2; mi++)
                LDSM4(af[mi][0], af[mi][1], af[mi][2], af[mi][3],
                      sA + (uint32_t)((arow + mi * 16) * GP + k0 + acol) * 2);
#pragma unroll
            for (int p = 0; p < 4; p++)
                LDSM4(bf[2 * p][0], bf[2 * p][1], bf[2 * p + 1][0], bf[2 * p + 1][1],
                      sB + (uint32_t)((brow + p * 16) * GP + k0 + bcol) * 2);
#pragma unroll
            for (int mi = 0; mi < 2; mi++)
#pragma unroll
                for (int nj = 0; nj < 8; nj++)
                    mma_h16(acc[mi][nj], af[mi], bf[nj]);
        }
        if (c + 1 < NC) {
            if (c + 2 < NC) CP_WAIT1(); else CP_WAIT0();
            __syncthreads();
        }
    }

    // epilogue
#pragma unroll
    for (int mi = 0; mi < 2; mi++) {
        int r0 = bm + wm * 32 + mi * 16 + g;
#pragma unroll
        for (int nj = 0; nj < 8; nj++) {
            int col = bn + wn * 64 + nj * 8 + tig * 2;
            float b0 = bias[col], b1 = bias[col + 1];
            if (r0 < M) {
                float2 v = make_float2(acc[mi][nj][0] + b0, acc[mi][nj][1] + b1);
                *(float2*)&C[(size_t)r0 * N + col] = v;
            }
            if (r0 + 8 < M) {
                float2 v = make_float2(acc[mi][nj][2] + b0, acc[mi][nj][3] + b1);
                *(float2*)&C[(size_t)(r0 + 8) * N + col] = v;
            }
        }
    }
}

// ---------------- persistent LSTM recurrence (fp16 mma) ----------------
#define HP 520
#define RP 133
#define LSTM_SMEM ((16 + 64) * HP * 2 + 64 * RP * 4)

__global__ void __launch_bounds__(256, 1)
lstm_mma(const float* __restrict__ W_hh) {
    extern __shared__ char sm8[];
    __half* wsh = (__half*)sm8;
    __half* hsh = (__half*)(sm8 + 16 * HP * 2);
    float*  red = (float*)(sm8 + (16 + 64) * HP * 2);

    const int tid = threadIdx.x, lane = tid & 31, wid = tid >> 5;
    const int g = lane >> 2, tig = lane & 3;
    const int j0 = blockIdx.x * 4;
    const int kw = wid * 64;
    const int fb = tid & 63, fch = tid >> 6;
    const int cb = tid >> 2, cl = tid & 3;

#pragma unroll
    for (int i = 0; i < 32; i++) {
        int idx = tid + (i << 8);
        int r = idx >> 9, k = idx & 511;
        int wrow = ((r >> 2) << 9) + j0 + (r & 3);
        wsh[r * HP + k] = __float2half(W_hh[(size_t)wrow * HDIM + k]);
    }
    __syncthreads();

    uint32_t breg[2][4][2];
#pragma unroll
    for (int nj = 0; nj < 2; nj++)
#pragma unroll
        for (int kk = 0; kk < 4; kk++) {
            const __half* p = &wsh[(nj * 8 + g) * HP + kw + kk * 16 + tig * 2];
            breg[nj][kk][0] = *(const uint32_t*)p;
            breg[nj][kk][1] = *(const uint32_t*)(p + 8);
        }

    float c_reg = 0.f;
    for (int t = 0; t < TSTEPS; t++) {
        if (t > 0) {
            if (tid == 0) {
                volatile unsigned* p = &g_cnt[t - 1];
                while (*p < 128u) { __nanosleep(32); }
                __threadfence();
            }
            __syncthreads();
        }
        const float* Gt = &g_G[((size_t)t * BATCH + cb) * GDIM + j0 + cl];
        float gI = __ldg(Gt);
        float gF = __ldg(Gt + 512);
        float gG = __ldg(Gt + 1024);
        float gO = __ldg(Gt + 1536);

        const __half* hsrc = g_hH[t & 1];
#pragma unroll
        for (int i = 0; i < 16; i++) {
            uint4 v = __ldcg((const uint4*)&hsrc[fb * HDIM + fch * 128 + i * 8]);
            *(uint4*)&hsh[fb * HP + fch * 128 + i * 8] = v;
        }
        __syncthreads();

        float acc[4][2][4];
#pragma unroll
        for (int mi = 0; mi < 4; mi++)
#pragma unroll
            for (int nj = 0; nj < 2; nj++)
#pragma unroll
                for (int i = 0; i < 4; i++) acc[mi][nj][i] = 0.f;
#pragma unroll
        for (int mi = 0; mi < 4; mi++) {
#pragma unroll
            for (int kk = 0; kk < 4; kk++) {
                const __half* base = &hsh[(mi * 16 + g) * HP + kw + kk * 16 + tig * 2];
                uint32_t a[4];
                a[0] = *(const uint32_t*)(base);
                a[1] = *(const uint32_t*)(base + 8 * HP);
                a[2] = *(const uint32_t*)(base + 8);
                a[3] = *(const uint32_t*)(base + 8 * HP + 8);
                mma_h16(acc[mi][0], a, breg[0][kk]);
                mma_h16(acc[mi][1], a, breg[1][kk]);
            }
        }
#pragma unroll
        for (int mi = 0; mi < 4; mi++)
#pragma unroll
            for (int nj = 0; nj < 2; nj++) {
                int m0 = mi * 16 + g, n0 = nj * 8 + tig * 2;
                float* rp = &red[m0 * RP + wid * 16 + n0];
                rp[0] = acc[mi][nj][0];
                rp[1] = acc[mi][nj][1];
                rp[8 * RP] = acc[mi][nj][2];
                rp[8 * RP + 1] = acc[mi][nj][3];
            }
        __syncthreads();

        float s0 = 0.f, s1 = 0.f, s2 = 0.f, s3 = 0.f;
#pragma unroll
        for (int w = 0; w < 8; w++) {
            const float* rp = &red[cb * RP + w * 16 + cl];
            s0 += rp[0]; s1 += rp[4]; s2 += rp[8]; s3 += rp[12];
        }
        float xi = gI + s0, xf = gF + s1, xg = gG + s2, xo = gO + s3;
        float cn = sigf(xf) * c_reg + sigf(xi) * tanhf(xg);
        float hn = sigf(xo) * tanhf(cn);
        c_reg = cn;
        g_hH[(t + 1) & 1][cb * HDIM + j0 + cl] = __float2half(hn);
        if (t >= MAXFRAME && t < MAXFRAME + CAPLEN - 1)
            g_dechH[((size_t)cb * (CAPLEN - 1) + (t - MAXFRAME)) * HDIM + j0 + cl] = __float2half(hn);
        __threadfence();
        __syncthreads();
        if (tid == 0) atomicAdd(&g_cnt[t], 1u);
    }
}

// ---------------- launch ----------------
extern "C" void kernel_launch(void* const* d_in, const int* in_sizes, int n_in,
                              void* d_out, int out_size) {
    const float* feature   = (const float*)d_in[0];
    const int*   captions  = (const int*)d_in[1];
    const float* embedding = (const float*)d_in[2];
    const float* W_ih      = (const float*)d_in[3];
    const float* W_hh      = (const float*)d_in[4];
    const float* b_ih      = (const float*)d_in[5];
    const float* b_hh      = (const float*)d_in[6];
    const float* W_lin     = (const float*)d_in[7];
    const float* b_lin     = (const float*)d_in[8];
    float* out = (float*)d_out;

    cudaFuncSetAttribute(h16_gemm, cudaFuncAttributeMaxDynamicSharedMemorySize, GEMM_SMEM);
    cudaFuncSetAttribute(lstm_mma, cudaFuncAttributeMaxDynamicSharedMemorySize, LSTM_SMEM);

    void *pXh, *pG, *pBias, *pWih, *pWlin, *pDech;
    cudaGetSymbolAddress(&pXh, g_Xh);
    cudaGetSymbolAddress(&pG, g_G);
    cudaGetSymbolAddress(&pBias, g_bias);
    cudaGetSymbolAddress(&pWih, g_WihH);
    cudaGetSymbolAddress(&pWlin, g_WlinH);
    cudaGetSymbolAddress(&pDech, g_dechH);

    build_xh<<<1920, 256>>>(feature, captions, embedding);
    prep_kernel<<<64, 256>>>(b_ih, b_hh);
    conv_h<<<1024, 256>>>(W_ih, (__half*)pWih, GDIM * XDIM / 8);
    conv_h<<<8000, 256>>>(W_lin, (__half*)pWlin, VOCAB * HDIM / 8);
    h16_gemm<<<dim3(GDIM / 128, (TSTEPS * BATCH) / 128), 256, GEMM_SMEM>>>(
        (const __half*)pXh, (const __half*)pWih, (const float*)pBias, (float*)pG,
        TSTEPS * BATCH, GDIM, XDIM);
    lstm_mma<<<128, 256, LSTM_SMEM>>>(W_hh);
    h16_gemm<<<dim3(VOCAB / 128, OUTROWS_PAD / 128), 256, GEMM_SMEM>>>(
        (const __half*)pDech, (const __half*)pWlin, b_lin, out,
        OUTROWS, VOCAB, HDIM);
}

// round 7
// speedup vs baseline: 4.1836x; 1.3457x over previous
#include <cuda_runtime.h>
#include <cuda_fp16.h>
#include <math.h>
#include <stdint.h>

#define BATCH 64
#define TSTEPS 60
#define MAXFRAME 40
#define CAPLEN 20
#define HDIM 512
#define XDIM 1024
#define GDIM 2048
#define VOCAB 32000
#define OUTROWS 1216
#define OUTROWS_PAD 1280
#define GH 520                               // padded pitch of global/smem h rows (halves)

// ---------------- device scratch ----------------
__device__ __half g_Xh[TSTEPS * BATCH * XDIM];
__device__ float  g_G[TSTEPS * BATCH * GDIM];
__device__ float  g_bias[GDIM];
__device__ __half g_WihH[GDIM * XDIM];
__device__ __half g_WlinH[VOCAB * HDIM];
__device__ __half g_hH[2][BATCH * GH];       // padded, pitch 520
__device__ __half g_dechH[OUTROWS_PAD * HDIM];
__device__ unsigned g_cnt[TSTEPS];

// ---------------- helpers ----------------
__device__ __forceinline__ uint32_t f2h2(float a, float b) {
    __half2 h = __floats2half2_rn(a, b);
    return *(uint32_t*)&h;
}
__device__ __forceinline__ void mma_h16(float* c, const uint32_t* a, const uint32_t* b) {
    asm volatile(
        "mma.sync.aligned.m16n8k16.row.col.f32.f16.f16.f32 "
        "{%0,%1,%2,%3}, {%4,%5,%6,%7}, {%8,%9}, {%0,%1,%2,%3};"
        : "+f"(c[0]), "+f"(c[1]), "+f"(c[2]), "+f"(c[3])
        : "r"(a[0]), "r"(a[1]), "r"(a[2]), "r"(a[3]), "r"(b[0]), "r"(b[1]));
}
__device__ __forceinline__ float sigf(float x) { return 1.f / (1.f + __expf(-x)); }
__device__ __forceinline__ void cp16(uint32_t d, const void* s) {
    asm volatile("cp.async.cg.shared.global [%0], [%1], 16;" :: "r"(d), "l"(s));
}
#define CP_COMMIT() asm volatile("cp.async.commit_group;" ::: "memory")
#define CP_WAIT1()  asm volatile("cp.async.wait_group 1;" ::: "memory")
#define CP_WAIT0()  asm volatile("cp.async.wait_group 0;" ::: "memory")
#define LDSM4(r0, r1, r2, r3, a) \
    asm volatile("ldmatrix.sync.aligned.m8n8.x4.shared.b16 {%0,%1,%2,%3}, [%4];" \
        : "=r"(r0), "=r"(r1), "=r"(r2), "=r"(r3) : "r"(a))
#define MBAR_INIT(mb, c) asm volatile("mbarrier.init.shared.b64 [%0], %1;" :: "r"(mb), "r"(c) : "memory")
__device__ __forceinline__ void mbar_wait(uint32_t mb, uint32_t parity) {
    asm volatile(
        "{\n\t.reg .pred P;\n\t"
        "LAB_W%=:\n\t"
        "mbarrier.try_wait.parity.acquire.cta.shared::cta.b64 P, [%0], %1, 0x989680;\n\t"
        "@P bra.uni LAB_D%=;\n\t"
        "bra.uni LAB_W%=;\n\t"
        "LAB_D%=:\n\t}" :: "r"(mb), "r"(parity) : "memory");
}
__device__ __forceinline__ void bulk_ld(uint32_t dst, const void* src, uint32_t bytes, uint32_t mb) {
    asm volatile(
        "cp.async.bulk.shared::cluster.global.mbarrier::complete_tx::bytes [%0], [%1], %2, [%3];"
        :: "r"(dst), "l"(src), "r"(bytes), "r"(mb) : "memory");
}

// ---------------- build xs (fp16) ----------------
__global__ void build_xh(const float* __restrict__ feature,
                         const int* __restrict__ captions,
                         const float* __restrict__ embedding) {
    int idx = blockIdx.x * 256 + threadIdx.x;
    int r = idx >> 7, c8 = idx & 127;
    int t = r >> 6, b = r & 63;
    float4 lo = make_float4(0.f, 0.f, 0.f, 0.f), hi = lo;
    if (c8 < 64) {
        if (t >= MAXFRAME) {
            int cap = captions[b * CAPLEN + (t - MAXFRAME)];
            const float4* src = (const float4*)&embedding[(size_t)cap * HDIM + c8 * 8];
            lo = src[0]; hi = src[1];
        }
    } else {
        const float4* src = (const float4*)&feature[((size_t)b * TSTEPS + t) * HDIM + (c8 - 64) * 8];
        lo = src[0]; hi = src[1];
    }
    uint4 o;
    o.x = f2h2(lo.x, lo.y); o.y = f2h2(lo.z, lo.w);
    o.z = f2h2(hi.x, hi.y); o.w = f2h2(hi.z, hi.w);
    ((uint4*)g_Xh)[idx] = o;
}

// ---------------- fp32 -> fp16 convert ----------------
__global__ void conv_h(const float* __restrict__ s, __half* __restrict__ d, int n8) {
    int i = blockIdx.x * 256 + threadIdx.x;
    if (i < n8) {
        float4 a = ((const float4*)s)[i * 2];
        float4 b = ((const float4*)s)[i * 2 + 1];
        uint4 o;
        o.x = f2h2(a.x, a.y); o.y = f2h2(a.z, a.w);
        o.z = f2h2(b.x, b.y); o.w = f2h2(b.z, b.w);
        ((uint4*)d)[i] = o;
    }
}

// ---------------- prep ----------------
__global__ void prep_kernel(const float* __restrict__ b_ih, const float* __restrict__ b_hh) {
    int idx = blockIdx.x * 256 + threadIdx.x;      // 16384 threads
    // zero both padded h buffers: 2*64*520 halves = 33280 u32
    ((uint32_t*)g_hH)[idx] = 0u;
    ((uint32_t*)g_hH)[idx + 16384] = 0u;
    if (idx < 512) ((uint32_t*)g_hH)[idx + 32768] = 0u;
    ((uint32_t*)g_dechH)[OUTROWS * HDIM / 2 + idx] = 0u;  // zero pad rows
    if (idx < GDIM) g_bias[idx] = b_ih[idx] + b_hh[idx];
    if (idx < TSTEPS) g_cnt[idx] = 0u;
}

// ---------------- fp16 mma GEMM (cp.async 3-stage + ldmatrix) ----------------
#define GP 40
#define STAGE_B (128 * GP * 2 * 2)
#define GEMM_SMEM (3 * STAGE_B)

__global__ void __launch_bounds__(256)
h16_gemm(const __half* __restrict__ A, const __half* __restrict__ B,
         const float* __restrict__ bias, float* __restrict__ C,
         int M, int N, int K) {
    extern __shared__ __half sh[];
    uint32_t sbase;
    asm("{ .reg .u64 t; cvta.to.shared.u64 t, %1; cvt.u32.u64 %0, t; }" : "=r"(sbase) : "l"(sh));

    const int tid = threadIdx.x, lane = tid & 31, wid = tid >> 5;
    const int wm = wid & 3, wn = wid >> 2;
    const int g = lane >> 2, tig = lane & 3;
    const int bm = blockIdx.y * 128, bn = blockIdx.x * 128;

    const int frow = tid >> 1, fho = (tid & 1) * 16;
    const __half* gA = &A[(size_t)(bm + frow) * K + fho];
    const __half* gB = &B[(size_t)(bn + frow) * K + fho];
    const uint32_t fsoff = (uint32_t)(frow * GP + fho) * 2;

    const int arow = wm * 32 + ((lane & 7) | (((lane >> 3) & 1) << 3));
    const int acol = (lane >> 4) * 8;
    const int brow = wn * 64 + (lane & 7) + ((lane >> 4) << 3);
    const int bcol = ((lane >> 3) & 1) * 8;

    float acc[2][8][4];
#pragma unroll
    for (int mi = 0; mi < 2; mi++)
#pragma unroll
        for (int nj = 0; nj < 8; nj++)
#pragma unroll
            for (int i = 0; i < 4; i++) acc[mi][nj][i] = 0.f;

    const int NC = K >> 5;
#pragma unroll
    for (int s = 0; s < 2; s++) {
        uint32_t sa = sbase + s * STAGE_B + fsoff;
        uint32_t sb = sa + 128 * GP * 2;
        const __half* pa = gA + (s << 5);
        const __half* pb = gB + (s << 5);
        cp16(sa, pa); cp16(sa + 16, pa + 8);
        cp16(sb, pb); cp16(sb + 16, pb + 8);
        CP_COMMIT();
    }
    CP_WAIT1();
    __syncthreads();

    for (int c = 0; c < NC; c++) {
        const int cur = c % 3;
        if (c + 2 < NC) {
            const int ns = (c + 2) % 3;
            uint32_t sa = sbase + ns * STAGE_B + fsoff;
            uint32_t sb = sa + 128 * GP * 2;
            const __half* pa = gA + ((c + 2) << 5);
            const __half* pb = gB + ((c + 2) << 5);
            cp16(sa, pa); cp16(sa + 16, pa + 8);
            cp16(sb, pb); cp16(sb + 16, pb + 8);
            CP_COMMIT();
        }
        const uint32_t sA = sbase + cur * STAGE_B;
        const uint32_t sB = sA + 128 * GP * 2;
#pragma unroll
        for (int kk = 0; kk < 2; kk++) {
            const int k0 = kk * 16;
            uint32_t af[2][4], bf[8][2];
#pragma unroll
            for (int mi = 0; mi < 2; mi++)
                LDSM4(af[mi][0], af[mi][1], af[mi][2], af[mi][3],
                      sA + (uint32_t)((arow + mi * 16) * GP + k0 + acol) * 2);
#pragma unroll
            for (int p = 0; p < 4; p++)
                LDSM4(bf[2 * p][0], bf[2 * p][1], bf[2 * p + 1][0], bf[2 * p + 1][1],
                      sB + (uint32_t)((brow + p * 16) * GP + k0 + bcol) * 2);
#pragma unroll
            for (int mi = 0; mi < 2; mi++)
#pragma unroll
                for (int nj = 0; nj < 8; nj++)
                    mma_h16(acc[mi][nj], af[mi], bf[nj]);
        }
        if (c + 1 < NC) {
            if (c + 2 < NC) CP_WAIT1(); else CP_WAIT0();
            __syncthreads();
        }
    }

#pragma unroll
    for (int mi = 0; mi < 2; mi++) {
        int r0 = bm + wm * 32 + mi * 16 + g;
#pragma unroll
        for (int nj = 0; nj < 8; nj++) {
            int col = bn + wn * 64 + nj * 8 + tig * 2;
            float b0 = bias[col], b1 = bias[col + 1];
            if (r0 < M) {
                float2 v = make_float2(acc[mi][nj][0] + b0, acc[mi][nj][1] + b1);
                *(float2*)&C[(size_t)r0 * N + col] = v;
            }
            if (r0 + 8 < M) {
                float2 v = make_float2(acc[mi][nj][2] + b0, acc[mi][nj][3] + b1);
                *(float2*)&C[(size_t)(r0 + 8) * N + col] = v;
            }
        }
    }
}

// ---------------- persistent LSTM recurrence (fp16 mma + bulk h broadcast) ----------------
// smem: hsh [64][GH] halves (66560 B, first, 16B aligned) | wsh [16][GH] (16640 B)
//       red [64][RP] f32 (34048 B) | mbar (8 B)
#define RP 133
#define HSH_B (64 * GH * 2)
#define WSH_B (16 * GH * 2)
#define RED_B (64 * RP * 4)
#define LSTM_SMEM (HSH_B + WSH_B + RED_B + 16)
#define H_BYTES (BATCH * GH * 2)              // 66560

__global__ void __launch_bounds__(256, 1)
lstm_mma(const float* __restrict__ W_hh) {
    extern __shared__ char sm8[];
    __half* hsh = (__half*)sm8;
    __half* wsh = (__half*)(sm8 + HSH_B);
    float*  red = (float*)(sm8 + HSH_B + WSH_B);
    uint32_t sbase;
    asm("{ .reg .u64 t; cvta.to.shared.u64 t, %1; cvt.u32.u64 %0, t; }" : "=r"(sbase) : "l"(sm8));
    const uint32_t MB = sbase + HSH_B + WSH_B + RED_B;

    const int tid = threadIdx.x, lane = tid & 31, wid = tid >> 5;
    const int g = lane >> 2, tig = lane & 3;
    const int j0 = blockIdx.x * 4;
    const int kw = wid * 64;
    const int cb = tid >> 2, cl = tid & 3;

    // load W slice -> wsh (pitch GH keeps the conflict-free pattern: GH*2 B = 1040 ≡ 4 words mod 32)
#pragma unroll
    for (int i = 0; i < 32; i++) {
        int idx = tid + (i << 8);
        int r = idx >> 9, k = idx & 511;
        int wrow = ((r >> 2) << 9) + j0 + (r & 3);
        wsh[r * GH + k] = __float2half(W_hh[(size_t)wrow * HDIM + k]);
    }
    if (tid == 0) MBAR_INIT(MB, 1);
    __syncthreads();

    uint32_t breg[2][4][2];
#pragma unroll
    for (int nj = 0; nj < 2; nj++)
#pragma unroll
        for (int kk = 0; kk < 4; kk++) {
            const __half* p = &wsh[(nj * 8 + g) * GH + kw + kk * 16 + tig * 2];
            breg[nj][kk][0] = *(const uint32_t*)p;
            breg[nj][kk][1] = *(const uint32_t*)(p + 8);
        }

    float c_reg = 0.f;
    uint32_t mph = 0;
    for (int t = 0; t < TSTEPS; t++) {
        // prefetch x-side gates (independent of h — overlaps the wait)
        const float* Gt = &g_G[((size_t)t * BATCH + cb) * GDIM + j0 + cl];
        float gI = __ldg(Gt);
        float gF = __ldg(Gt + 512);
        float gG = __ldg(Gt + 1024);
        float gO = __ldg(Gt + 1536);

        if (tid == 0) {
            if (t > 0) {   // wait for all CTAs to publish h[t]
                unsigned v;
                do {
                    asm volatile("ld.acquire.gpu.global.u32 %0, [%1];"
                                 : "=r"(v) : "l"(&g_cnt[t - 1]));
                    if (v >= 128u) break;
                    __nanosleep(32);
                } while (1);
            }
            asm volatile("fence.proxy.async;" ::: "memory");
            asm volatile("mbarrier.arrive.expect_tx.shared.b64 _, [%0], %1;"
                         :: "r"(MB), "r"((uint32_t)H_BYTES) : "memory");
            bulk_ld(sbase, &g_hH[t & 1][0], H_BYTES, MB);
        }
        mbar_wait(MB, mph);
        mph ^= 1;

        // mma: warp computes 64(batch) x 16(gate) over its 64-K slice
        float acc[4][2][4];
#pragma unroll
        for (int mi = 0; mi < 4; mi++)
#pragma unroll
            for (int nj = 0; nj < 2; nj++)
#pragma unroll
                for (int i = 0; i < 4; i++) acc[mi][nj][i] = 0.f;
#pragma unroll
        for (int mi = 0; mi < 4; mi++) {
#pragma unroll
            for (int kk = 0; kk < 4; kk++) {
                const __half* base = &hsh[(mi * 16 + g) * GH + kw + kk * 16 + tig * 2];
                uint32_t a[4];
                a[0] = *(const uint32_t*)(base);
                a[1] = *(const uint32_t*)(base + 8 * GH);
                a[2] = *(const uint32_t*)(base + 8);
                a[3] = *(const uint32_t*)(base + 8 * GH + 8);
                mma_h16(acc[mi][0], a, breg[0][kk]);
                mma_h16(acc[mi][1], a, breg[1][kk]);
            }
        }
#pragma unroll
        for (int mi = 0; mi < 4; mi++)
#pragma unroll
            for (int nj = 0; nj < 2; nj++) {
                int m0 = mi * 16 + g, n0 = nj * 8 + tig * 2;
                float* rp = &red[m0 * RP + wid * 16 + n0];
                rp[0] = acc[mi][nj][0];
                rp[1] = acc[mi][nj][1];
                rp[8 * RP] = acc[mi][nj][2];
                rp[8 * RP + 1] = acc[mi][nj][3];
            }
        __syncthreads();

        float s0 = 0.f, s1 = 0.f, s2 = 0.f, s3 = 0.f;
#pragma unroll
        for (int w = 0; w < 8; w++) {
            const float* rp = &red[cb * RP + w * 16 + cl];
            s0 += rp[0]; s1 += rp[4]; s2 += rp[8]; s3 += rp[12];
        }
        float xi = gI + s0, xf = gF + s1, xg = gG + s2, xo = gO + s3;
        float cn = sigf(xf) * c_reg + sigf(xi) * tanhf(xg);
        float hn = sigf(xo) * tanhf(cn);
        c_reg = cn;
        g_hH[(t + 1) & 1][cb * GH + j0 + cl] = __float2half(hn);
        if (t >= MAXFRAME && t < MAXFRAME + CAPLEN - 1)
            g_dechH[((size_t)cb * (CAPLEN - 1) + (t - MAXFRAME)) * HDIM + j0 + cl] = __float2half(hn);
        __syncthreads();   // all stores done (also guards red reuse)
        if (tid == 0)
            asm volatile("red.release.gpu.global.add.u32 [%0], 1;" :: "l"(&g_cnt[t]) : "memory");
    }
}

// ---------------- launch ----------------
extern "C" void kernel_launch(void* const* d_in, const int* in_sizes, int n_in,
                              void* d_out, int out_size) {
    const float* feature   = (const float*)d_in[0];
    const int*   captions  = (const int*)d_in[1];
    const float* embedding = (const float*)d_in[2];
    const float* W_ih      = (const float*)d_in[3];
    const float* W_hh      = (const float*)d_in[4];
    const float* b_ih      = (const float*)d_in[5];
    const float* b_hh      = (const float*)d_in[6];
    const float* W_lin     = (const float*)d_in[7];
    const float* b_lin     = (const float*)d_in[8];
    float* out = (float*)d_out;

    cudaFuncSetAttribute(h16_gemm, cudaFuncAttributeMaxDynamicSharedMemorySize, GEMM_SMEM);
    cudaFuncSetAttribute(lstm_mma, cudaFuncAttributeMaxDynamicSharedMemorySize, LSTM_SMEM);

    void *pXh, *pG, *pBias, *pWih, *pWlin, *pDech;
    cudaGetSymbolAddress(&pXh, g_Xh);
    cudaGetSymbolAddress(&pG, g_G);
    cudaGetSymbolAddress(&pBias, g_bias);
    cudaGetSymbolAddress(&pWih, g_WihH);
    cudaGetSymbolAddress(&pWlin, g_WlinH);
    cudaGetSymbolAddress(&pDech, g_dechH);

    build_xh<<<1920, 256>>>(feature, captions, embedding);
    prep_kernel<<<64, 256>>>(b_ih, b_hh);
    conv_h<<<1024, 256>>>(W_ih, (__half*)pWih, GDIM * XDIM / 8);
    conv_h<<<8000, 256>>>(W_lin, (__half*)pWlin, VOCAB * HDIM / 8);
    h16_gemm<<<dim3(GDIM / 128, (TSTEPS * BATCH) / 128), 256, GEMM_SMEM>>>(
        (const __half*)pXh, (const __half*)pWih, (const float*)pBias, (float*)pG,
        TSTEPS * BATCH, GDIM, XDIM);
    lstm_mma<<<128, 256, LSTM_SMEM>>>(W_hh);
    h16_gemm<<<dim3(VOCAB / 128, OUTROWS_PAD / 128), 256, GEMM_SMEM>>>(
        (const __half*)pDech, (const __half*)pWlin, b_lin, out,
        OUTROWS, VOCAB, HDIM);
}